// round 6
// baseline (speedup 1.0000x reference)
#include <cuda_runtime.h>
#include <cstdint>

#define NN   4096
#define INF_ 256
#define OF   128
#define KH   3
#define ALPHA 0.2f
#define CS   4               // column splits
#define CPC  (NN/CS)         // cols per split (1024)
#define CT   64              // k-tile (cols per stage)
#define MT   128             // rows per block
#define NTILES (CPC/CT)      // 16
#define VPAD 136             // V_s row stride in floats (bank-conflict free)

// scratch (device globals — no allocation allowed)
__device__ float    g_Wh[KH][NN][OF];       // Whnew fp32
__device__ float    g_Vt[KH][NN][OF];       // Whnew pre-rounded to tf32
__device__ float4   g_EF[KH][NN];           // {exp(f1), exp(a*f1), exp(f2), exp(a*f2)}
__device__ unsigned g_mbits[KH][NN][NN/32]; // bit-packed mask
__device__ float    g_num[CS][KH][NN][OF];
__device__ float    g_den[CS][KH][NN];

__device__ __forceinline__ unsigned f2tf32(float x){
    unsigned r; asm("cvt.rna.tf32.f32 %0, %1;" : "=r"(r) : "f"(x)); return r;
}
__device__ __forceinline__ void mma_tf32(float (&d)[4], const unsigned (&a)[4],
                                         unsigned b0, unsigned b1){
    asm volatile("mma.sync.aligned.m16n8k8.row.col.f32.tf32.tf32.f32 "
        "{%0,%1,%2,%3},{%4,%5,%6,%7},{%8,%9},{%0,%1,%2,%3};\n"
        : "+f"(d[0]), "+f"(d[1]), "+f"(d[2]), "+f"(d[3])
        : "r"(a[0]), "r"(a[1]), "r"(a[2]), "r"(a[3]), "r"(b0), "r"(b1));
}
__device__ __forceinline__ void cpa16(void* dst, const void* src){
    unsigned d = (unsigned)__cvta_generic_to_shared(dst);
    asm volatile("cp.async.cg.shared.global [%0], [%1], 16;\n" :: "r"(d), "l"(src));
}
__device__ __forceinline__ void cpa8(void* dst, const void* src){
    unsigned d = (unsigned)__cvta_generic_to_shared(dst);
    asm volatile("cp.async.ca.shared.global [%0], [%1], 8;\n" :: "r"(d), "l"(src));
}

// ---------------- Kernel 0: pack mask into bits (streaming) ----------------
__global__ __launch_bounds__(256) void k_pack(const int* __restrict__ mask){
    size_t wbase = (size_t)blockIdx.x*64 + (size_t)(threadIdx.x>>5)*8;
    int l = threadIdx.x & 31;
    const int* p = mask + wbase*32;
    int v[8];
    #pragma unroll
    for (int i=0;i<8;i++) v[i] = p[(size_t)i*32 + l];
    unsigned b[8];
    #pragma unroll
    for (int i=0;i<8;i++) b[i] = __ballot_sync(0xffffffffu, v[i] > 0);
    if (l==0){
        unsigned* dst = ((unsigned*)g_mbits) + wbase;
        uint4 lo = make_uint4(b[0],b[1],b[2],b[3]);
        uint4 hi = make_uint4(b[4],b[5],b[6],b[7]);
        *(uint4*)(dst)   = lo;
        *(uint4*)(dst+4) = hi;
    }
}

// ---------------- Kernel 1: Whnew = h @ W_i (fp32) + tf32-rounded copy ----------------
__global__ __launch_bounds__(256) void k_gemm(const float* __restrict__ h,
                                              const float* __restrict__ W){
    int hop = blockIdx.y;
    int r0  = blockIdx.x * 64;
    __shared__ float hs[64][32];
    __shared__ float ws[32][128];
    int tid = threadIdx.x;
    int ty = tid >> 5, tx = tid & 31;
    float acc[8][4];
    #pragma unroll
    for (int i=0;i<8;i++){ acc[i][0]=0.f;acc[i][1]=0.f;acc[i][2]=0.f;acc[i][3]=0.f; }

    for (int k0=0; k0<INF_; k0+=32){
        #pragma unroll
        for (int i=0;i<2;i++){
            int f4 = tid + i*256;
            int row = f4>>3, c4 = f4&7;
            *(float4*)&hs[row][c4*4] =
                *(const float4*)&h[(size_t)(r0+row)*INF_ + k0 + c4*4];
        }
        #pragma unroll
        for (int i=0;i<4;i++){
            int f4 = tid + i*256;
            int row = f4>>5, c4 = f4&31;
            *(float4*)&ws[row][c4*4] =
                *(const float4*)&W[(size_t)(hop*INF_ + k0 + row)*OF + c4*4];
        }
        __syncthreads();
        #pragma unroll
        for (int k=0;k<32;k++){
            float4 w4 = *(const float4*)&ws[k][tx*4];
            #pragma unroll
            for (int ii=0;ii<8;ii++){
                float hv = hs[ty*8+ii][k];
                acc[ii][0] += hv*w4.x; acc[ii][1] += hv*w4.y;
                acc[ii][2] += hv*w4.z; acc[ii][3] += hv*w4.w;
            }
        }
        __syncthreads();
    }
    #pragma unroll
    for (int ii=0;ii<8;ii++){
        int r = r0 + ty*8 + ii;
        float4 o = make_float4(acc[ii][0],acc[ii][1],acc[ii][2],acc[ii][3]);
        *(float4*)&g_Wh[hop][r][tx*4] = o;
        float4 t = make_float4(__uint_as_float(f2tf32(o.x)), __uint_as_float(f2tf32(o.y)),
                               __uint_as_float(f2tf32(o.z)), __uint_as_float(f2tf32(o.w)));
        *(float4*)&g_Vt[hop][r][tx*4] = t;
    }
}

// ---------------- Kernel 2: f1,f2 per (hop,row) -> exp tables ----------------
__global__ __launch_bounds__(256) void k_f(const float* __restrict__ a){
    int gw   = blockIdx.x*8 + (threadIdx.x>>5);
    int lane = threadIdx.x & 31;
    int hop  = gw >> 12;
    int row  = gw & (NN-1);
    float4 wh = *(const float4*)&g_Wh[hop][row][lane*4];
    float4 a1 = *(const float4*)&a[(2*hop  )*OF + lane*4];
    float4 a2 = *(const float4*)&a[(2*hop+1)*OF + lane*4];
    float p1 = wh.x*a1.x + wh.y*a1.y + wh.z*a1.z + wh.w*a1.w;
    float p2 = wh.x*a2.x + wh.y*a2.y + wh.z*a2.z + wh.w*a2.w;
    #pragma unroll
    for (int o=16;o;o>>=1){
        p1 += __shfl_xor_sync(0xffffffffu,p1,o);
        p2 += __shfl_xor_sync(0xffffffffu,p2,o);
    }
    if (lane==0)
        g_EF[hop][row] = make_float4(expf(p1), expf(ALPHA*p1), expf(p2), expf(ALPHA*p2));
}

// ---------------- Kernel 3: fused masked-softmax-numerator @ V via tf32 MMA ----------------
// block = (rowblock MT=128, hop, colsplit); 256 threads = 8 warps, each owns one m16 group.
// Double-buffered cp.async pipeline for V tile / E2 / packed mask bits.
#define SM_V   (2*CT*VPAD)                    // floats
#define SM_E   (2*CT)                         // float4
#define SM_M   (2*MT)                         // uint2
#define SMEM_BYTES (SM_V*4 + SM_E*16 + SM_M*8)

__global__ __launch_bounds__(256, 2) void k_attn(){
    extern __shared__ char smem_raw[];
    float*  V_s = (float*)smem_raw;                       // [2][CT][VPAD]
    float4* E_s = (float4*)(smem_raw + SM_V*4);           // [2][CT]
    uint2*  M_s = (uint2*)(smem_raw + SM_V*4 + SM_E*16);  // [2][MT]

    const int hop = blockIdx.y, cs = blockIdx.z;
    const int rb  = blockIdx.x * MT;
    const int tid = threadIdx.x, w = tid>>5, l = tid&31;
    const int q4 = l>>2, t4 = l&3;

    // stage loader: full 64x128 V tile (8*256 float4), E2 chunk, mask bits
    auto stage = [&](int t, int b){
        int c0 = cs*CPC + t*CT;
        #pragma unroll
        for (int i=0;i<8;i++){
            int f4 = i*256 + tid;
            int row = f4>>5, c4 = f4&31;
            cpa16(&V_s[b*CT*VPAD + row*VPAD + c4*4], &g_Vt[hop][c0+row][c4*4]);
        }
        if (tid < CT)  cpa16(&E_s[b*CT + tid], &g_EF[hop][c0+tid]);
        if (tid < MT)  cpa8 (&M_s[b*MT + tid], &g_mbits[hop][rb+tid][c0>>5]);
        asm volatile("cp.async.commit_group;\n");
    };

    // per-warp row constants
    const int r0 = rb + w*16 + q4, r1 = r0 + 8;
    float4 ef0 = g_EF[hop][r0];
    float4 ef1 = g_EF[hop][r1];
    const float e1p0 = ef0.x, e1n0 = ef0.y, e1p1 = ef1.x, e1n1 = ef1.y;

    float acc[16][4];
    #pragma unroll
    for (int n=0;n<16;n++){ acc[n][0]=0;acc[n][1]=0;acc[n][2]=0;acc[n][3]=0; }
    float dsum0 = 0.f, dsum1 = 0.f;

    stage(0, 0);

    for (int t=0; t<NTILES; t++){
        int b = t & 1;
        if (t+1 < NTILES){
            stage(t+1, (t+1)&1);
            asm volatile("cp.async.wait_group 1;\n");
        } else {
            asm volatile("cp.async.wait_group 0;\n");
        }
        __syncthreads();

        uint2 mw0 = M_s[b*MT + w*16 + q4];
        uint2 mw1 = M_s[b*MT + w*16 + q4 + 8];
        const float* Vb = V_s + b*CT*VPAD;
        const float4* Eb = E_s + b*CT;

        #pragma unroll
        for (int k2=0;k2<8;k2++){
            const int cb = k2*8;
            float4 eA = Eb[cb + t4];
            float4 eB = Eb[cb + t4 + 4];
            float v00 = fmaxf(e1p0*eA.z, e1n0*eA.w);
            float v10 = fmaxf(e1p1*eA.z, e1n1*eA.w);
            float v01 = fmaxf(e1p0*eB.z, e1n0*eB.w);
            float v11 = fmaxf(e1p1*eB.z, e1n1*eB.w);
            // mask bit selection (word chosen at compile time per k2)
            unsigned wA0 = (k2<4)? mw0.x : mw0.y;
            unsigned wA1 = (k2<4)? mw1.x : mw1.y;
            unsigned wB0 = (k2<4)? mw0.x : mw0.y;   // cb+t4+4 <=31 for k2<=3
            unsigned wB1 = (k2<4)? mw1.x : mw1.y;
            int shA = (cb + t4) & 31;
            int shB = (cb + t4 + 4) & 31;
            unsigned fr[4];
            fr[0] = ((wA0>>shA)&1u) ? f2tf32(v00) : 0u;
            fr[1] = ((wA1>>shA)&1u) ? f2tf32(v10) : 0u;
            fr[2] = ((wB0>>shB)&1u) ? f2tf32(v01) : 0u;
            fr[3] = ((wB1>>shB)&1u) ? f2tf32(v11) : 0u;
            dsum0 += __uint_as_float(fr[0]) + __uint_as_float(fr[2]);
            dsum1 += __uint_as_float(fr[1]) + __uint_as_float(fr[3]);

            const float* vr0 = Vb + (cb+t4)*VPAD + q4;
            const float* vr1 = Vb + (cb+t4+4)*VPAD + q4;
            #pragma unroll
            for (int n=0;n<16;n++){
                mma_tf32(acc[n], fr,
                         __float_as_uint(vr0[n*8]),
                         __float_as_uint(vr1[n*8]));
            }
        }
        __syncthreads();
    }

    // denominators: reduce across t4 lanes (same rows)
    dsum0 += __shfl_xor_sync(0xffffffffu, dsum0, 1);
    dsum0 += __shfl_xor_sync(0xffffffffu, dsum0, 2);
    dsum1 += __shfl_xor_sync(0xffffffffu, dsum1, 1);
    dsum1 += __shfl_xor_sync(0xffffffffu, dsum1, 2);
    if (t4 == 0){
        g_den[cs][hop][r0] = dsum0;
        g_den[cs][hop][r1] = dsum1;
    }
    // numerators
    #pragma unroll
    for (int n=0;n<16;n++){
        int gc = n*8 + 2*t4;
        float2 lo; lo.x = acc[n][0]; lo.y = acc[n][1];
        float2 hi; hi.x = acc[n][2]; hi.y = acc[n][3];
        *(float2*)&g_num[cs][hop][r0][gc] = lo;
        *(float2*)&g_num[cs][hop][r1][gc] = hi;
    }
}

// ---------------- Kernel 4: combine hops + elu ----------------
__global__ __launch_bounds__(256) void k_comb(float* __restrict__ out){
    int idx = blockIdx.x*256 + threadIdx.x;
    int r = idx >> 7, c = idx & (OF-1);
    float z = 0.125f * g_Wh[2][r][c];
    float coef = 0.5f;
    #pragma unroll
    for (int h2=0; h2<KH; h2++){
        float num = 0.f, den = 1e-30f;
        #pragma unroll
        for (int s=0;s<CS;s++){ num += g_num[s][h2][r][c]; den += g_den[s][h2][r]; }
        z += coef * num / den;
        coef *= 0.5f;
    }
    out[idx] = (z > 0.f) ? z : expm1f(z);
}

extern "C" void kernel_launch(void* const* d_in, const int* in_sizes, int n_in,
                              void* d_out, int out_size){
    const float* h    = (const float*)d_in[0];
    const int*   mask = (const int*)  d_in[1];
    const float* W    = (const float*)d_in[2];
    const float* a    = (const float*)d_in[3];
    float* out = (float*)d_out;

    cudaFuncSetAttribute(k_attn, cudaFuncAttributeMaxDynamicSharedMemorySize, SMEM_BYTES);

    k_gemm<<<dim3(NN/64, KH), 256>>>(h, W);
    k_f<<<(KH*NN)/8, 256>>>(a);
    k_pack<<<(KH*(size_t)NN*NN/32)/64, 256>>>(mask);
    k_attn<<<dim3(NN/MT, KH, CS), 256, SMEM_BYTES>>>();
    k_comb<<<(NN*OF)/256, 256>>>(out);
}

// round 7
// speedup vs baseline: 1.0014x; 1.0014x over previous
#include <cuda_runtime.h>
#include <cstdint>

#define NN   4096
#define INF_ 256
#define OF   128
#define KH   3
#define ALPHA 0.2f
#define CS   4               // column splits
#define CPC  (NN/CS)         // cols per split (1024)
#define CT   64              // k-tile (cols per stage)
#define MT   128             // rows per block
#define NTILES (CPC/CT)      // 16
#define VPAD 136             // V_s row stride in floats (bank-conflict free)

// scratch (device globals — no allocation allowed)
__device__ float    g_Wh[KH][NN][OF];       // Whnew fp32
__device__ float    g_Vt[KH][NN][OF];       // Whnew pre-rounded to tf32
__device__ float4   g_EF[KH][NN];           // {exp(f1), exp(a*f1), exp(f2), exp(a*f2)}
__device__ unsigned g_mbits[KH][NN][NN/32]; // bit-packed mask
__device__ float    g_num[CS][KH][NN][OF];
__device__ float    g_den[CS][KH][NN];

__device__ __forceinline__ unsigned f2tf32(float x){
    unsigned r; asm("cvt.rna.tf32.f32 %0, %1;" : "=r"(r) : "f"(x)); return r;
}
__device__ __forceinline__ void mma_tf32(float (&d)[4], const unsigned (&a)[4],
                                         unsigned b0, unsigned b1){
    asm volatile("mma.sync.aligned.m16n8k8.row.col.f32.tf32.tf32.f32 "
        "{%0,%1,%2,%3},{%4,%5,%6,%7},{%8,%9},{%0,%1,%2,%3};\n"
        : "+f"(d[0]), "+f"(d[1]), "+f"(d[2]), "+f"(d[3])
        : "r"(a[0]), "r"(a[1]), "r"(a[2]), "r"(a[3]), "r"(b0), "r"(b1));
}
__device__ __forceinline__ void cpa16(void* dst, const void* src){
    unsigned d = (unsigned)__cvta_generic_to_shared(dst);
    asm volatile("cp.async.cg.shared.global [%0], [%1], 16;\n" :: "r"(d), "l"(src));
}
__device__ __forceinline__ void cpa8(void* dst, const void* src){
    unsigned d = (unsigned)__cvta_generic_to_shared(dst);
    asm volatile("cp.async.ca.shared.global [%0], [%1], 8;\n" :: "r"(d), "l"(src));
}

// ---------------- Kernel 0: pack mask into bits (streaming) ----------------
__global__ __launch_bounds__(256) void k_pack(const int* __restrict__ mask){
    size_t wbase = (size_t)blockIdx.x*64 + (size_t)(threadIdx.x>>5)*8;
    int l = threadIdx.x & 31;
    const int* p = mask + wbase*32;
    int v[8];
    #pragma unroll
    for (int i=0;i<8;i++) v[i] = p[(size_t)i*32 + l];
    unsigned b[8];
    #pragma unroll
    for (int i=0;i<8;i++) b[i] = __ballot_sync(0xffffffffu, v[i] > 0);
    if (l==0){
        unsigned* dst = ((unsigned*)g_mbits) + wbase;
        uint4 lo = make_uint4(b[0],b[1],b[2],b[3]);
        uint4 hi = make_uint4(b[4],b[5],b[6],b[7]);
        *(uint4*)(dst)   = lo;
        *(uint4*)(dst+4) = hi;
    }
}

// ---------------- Kernel 1: Whnew = h @ W_i (fp32) + tf32-rounded copy ----------------
__global__ __launch_bounds__(256) void k_gemm(const float* __restrict__ h,
                                              const float* __restrict__ W){
    int hop = blockIdx.y;
    int r0  = blockIdx.x * 64;
    __shared__ float hs[64][32];
    __shared__ float ws[32][128];
    int tid = threadIdx.x;
    int ty = tid >> 5, tx = tid & 31;
    float acc[8][4];
    #pragma unroll
    for (int i=0;i<8;i++){ acc[i][0]=0.f;acc[i][1]=0.f;acc[i][2]=0.f;acc[i][3]=0.f; }

    for (int k0=0; k0<INF_; k0+=32){
        #pragma unroll
        for (int i=0;i<2;i++){
            int f4 = tid + i*256;
            int row = f4>>3, c4 = f4&7;
            *(float4*)&hs[row][c4*4] =
                *(const float4*)&h[(size_t)(r0+row)*INF_ + k0 + c4*4];
        }
        #pragma unroll
        for (int i=0;i<4;i++){
            int f4 = tid + i*256;
            int row = f4>>5, c4 = f4&31;
            *(float4*)&ws[row][c4*4] =
                *(const float4*)&W[(size_t)(hop*INF_ + k0 + row)*OF + c4*4];
        }
        __syncthreads();
        #pragma unroll
        for (int k=0;k<32;k++){
            float4 w4 = *(const float4*)&ws[k][tx*4];
            #pragma unroll
            for (int ii=0;ii<8;ii++){
                float hv = hs[ty*8+ii][k];
                acc[ii][0] += hv*w4.x; acc[ii][1] += hv*w4.y;
                acc[ii][2] += hv*w4.z; acc[ii][3] += hv*w4.w;
            }
        }
        __syncthreads();
    }
    #pragma unroll
    for (int ii=0;ii<8;ii++){
        int r = r0 + ty*8 + ii;
        float4 o = make_float4(acc[ii][0],acc[ii][1],acc[ii][2],acc[ii][3]);
        *(float4*)&g_Wh[hop][r][tx*4] = o;
        float4 t = make_float4(__uint_as_float(f2tf32(o.x)), __uint_as_float(f2tf32(o.y)),
                               __uint_as_float(f2tf32(o.z)), __uint_as_float(f2tf32(o.w)));
        *(float4*)&g_Vt[hop][r][tx*4] = t;
    }
}

// ---------------- Kernel 2: f1,f2 per (hop,row) -> exp tables ----------------
__global__ __launch_bounds__(256) void k_f(const float* __restrict__ a){
    int gw   = blockIdx.x*8 + (threadIdx.x>>5);
    int lane = threadIdx.x & 31;
    int hop  = gw >> 12;
    int row  = gw & (NN-1);
    float4 wh = *(const float4*)&g_Wh[hop][row][lane*4];
    float4 a1 = *(const float4*)&a[(2*hop  )*OF + lane*4];
    float4 a2 = *(const float4*)&a[(2*hop+1)*OF + lane*4];
    float p1 = wh.x*a1.x + wh.y*a1.y + wh.z*a1.z + wh.w*a1.w;
    float p2 = wh.x*a2.x + wh.y*a2.y + wh.z*a2.z + wh.w*a2.w;
    #pragma unroll
    for (int o=16;o;o>>=1){
        p1 += __shfl_xor_sync(0xffffffffu,p1,o);
        p2 += __shfl_xor_sync(0xffffffffu,p2,o);
    }
    if (lane==0)
        g_EF[hop][row] = make_float4(expf(p1), expf(ALPHA*p1), expf(p2), expf(ALPHA*p2));
}

// ---------------- Kernel 3: fused masked-softmax-numerator @ V via tf32 MMA ----------------
// block = (rowblock MT=128, hop, colsplit); 256 threads = 8 warps, each owns one m16 group.
// Double-buffered cp.async pipeline for V tile / E2 / packed mask bits.
#define SM_V   (2*CT*VPAD)                    // floats
#define SM_E   (2*CT)                         // float4
#define SM_M   (2*MT)                         // uint2
#define SMEM_BYTES (SM_V*4 + SM_E*16 + SM_M*8)

__global__ __launch_bounds__(256, 2) void k_attn(){
    extern __shared__ char smem_raw[];
    float*  V_s = (float*)smem_raw;                       // [2][CT][VPAD]
    float4* E_s = (float4*)(smem_raw + SM_V*4);           // [2][CT]
    uint2*  M_s = (uint2*)(smem_raw + SM_V*4 + SM_E*16);  // [2][MT]

    const int hop = blockIdx.y, cs = blockIdx.z;
    const int rb  = blockIdx.x * MT;
    const int tid = threadIdx.x, w = tid>>5, l = tid&31;
    const int q4 = l>>2, t4 = l&3;

    // stage loader: full 64x128 V tile (8*256 float4), E2 chunk, mask bits
    auto stage = [&](int t, int b){
        int c0 = cs*CPC + t*CT;
        #pragma unroll
        for (int i=0;i<8;i++){
            int f4 = i*256 + tid;
            int row = f4>>5, c4 = f4&31;
            cpa16(&V_s[b*CT*VPAD + row*VPAD + c4*4], &g_Vt[hop][c0+row][c4*4]);
        }
        if (tid < CT)  cpa16(&E_s[b*CT + tid], &g_EF[hop][c0+tid]);
        if (tid < MT)  cpa8 (&M_s[b*MT + tid], &g_mbits[hop][rb+tid][c0>>5]);
        asm volatile("cp.async.commit_group;\n");
    };

    // per-warp row constants
    const int r0 = rb + w*16 + q4, r1 = r0 + 8;
    float4 ef0 = g_EF[hop][r0];
    float4 ef1 = g_EF[hop][r1];
    const float e1p0 = ef0.x, e1n0 = ef0.y, e1p1 = ef1.x, e1n1 = ef1.y;

    float acc[16][4];
    #pragma unroll
    for (int n=0;n<16;n++){ acc[n][0]=0;acc[n][1]=0;acc[n][2]=0;acc[n][3]=0; }
    float dsum0 = 0.f, dsum1 = 0.f;

    stage(0, 0);

    for (int t=0; t<NTILES; t++){
        int b = t & 1;
        if (t+1 < NTILES){
            stage(t+1, (t+1)&1);
            asm volatile("cp.async.wait_group 1;\n");
        } else {
            asm volatile("cp.async.wait_group 0;\n");
        }
        __syncthreads();

        uint2 mw0 = M_s[b*MT + w*16 + q4];
        uint2 mw1 = M_s[b*MT + w*16 + q4 + 8];
        const float* Vb = V_s + b*CT*VPAD;
        const float4* Eb = E_s + b*CT;

        #pragma unroll
        for (int k2=0;k2<8;k2++){
            const int cb = k2*8;
            float4 eA = Eb[cb + t4];
            float4 eB = Eb[cb + t4 + 4];
            float v00 = fmaxf(e1p0*eA.z, e1n0*eA.w);
            float v10 = fmaxf(e1p1*eA.z, e1n1*eA.w);
            float v01 = fmaxf(e1p0*eB.z, e1n0*eB.w);
            float v11 = fmaxf(e1p1*eB.z, e1n1*eB.w);
            // mask bit selection (word chosen at compile time per k2)
            unsigned wA0 = (k2<4)? mw0.x : mw0.y;
            unsigned wA1 = (k2<4)? mw1.x : mw1.y;
            unsigned wB0 = (k2<4)? mw0.x : mw0.y;   // cb+t4+4 <=31 for k2<=3
            unsigned wB1 = (k2<4)? mw1.x : mw1.y;
            int shA = (cb + t4) & 31;
            int shB = (cb + t4 + 4) & 31;
            unsigned fr[4];
            fr[0] = ((wA0>>shA)&1u) ? f2tf32(v00) : 0u;
            fr[1] = ((wA1>>shA)&1u) ? f2tf32(v10) : 0u;
            fr[2] = ((wB0>>shB)&1u) ? f2tf32(v01) : 0u;
            fr[3] = ((wB1>>shB)&1u) ? f2tf32(v11) : 0u;
            dsum0 += __uint_as_float(fr[0]) + __uint_as_float(fr[2]);
            dsum1 += __uint_as_float(fr[1]) + __uint_as_float(fr[3]);

            const float* vr0 = Vb + (cb+t4)*VPAD + q4;
            const float* vr1 = Vb + (cb+t4+4)*VPAD + q4;
            #pragma unroll
            for (int n=0;n<16;n++){
                mma_tf32(acc[n], fr,
                         __float_as_uint(vr0[n*8]),
                         __float_as_uint(vr1[n*8]));
            }
        }
        __syncthreads();
    }

    // denominators: reduce across t4 lanes (same rows)
    dsum0 += __shfl_xor_sync(0xffffffffu, dsum0, 1);
    dsum0 += __shfl_xor_sync(0xffffffffu, dsum0, 2);
    dsum1 += __shfl_xor_sync(0xffffffffu, dsum1, 1);
    dsum1 += __shfl_xor_sync(0xffffffffu, dsum1, 2);
    if (t4 == 0){
        g_den[cs][hop][r0] = dsum0;
        g_den[cs][hop][r1] = dsum1;
    }
    // numerators
    #pragma unroll
    for (int n=0;n<16;n++){
        int gc = n*8 + 2*t4;
        float2 lo; lo.x = acc[n][0]; lo.y = acc[n][1];
        float2 hi; hi.x = acc[n][2]; hi.y = acc[n][3];
        *(float2*)&g_num[cs][hop][r0][gc] = lo;
        *(float2*)&g_num[cs][hop][r1][gc] = hi;
    }
}

// ---------------- Kernel 4: combine hops + elu ----------------
__global__ __launch_bounds__(256) void k_comb(float* __restrict__ out){
    int idx = blockIdx.x*256 + threadIdx.x;
    int r = idx >> 7, c = idx & (OF-1);
    float z = 0.125f * g_Wh[2][r][c];
    float coef = 0.5f;
    #pragma unroll
    for (int h2=0; h2<KH; h2++){
        float num = 0.f, den = 1e-30f;
        #pragma unroll
        for (int s=0;s<CS;s++){ num += g_num[s][h2][r][c]; den += g_den[s][h2][r]; }
        z += coef * num / den;
        coef *= 0.5f;
    }
    out[idx] = (z > 0.f) ? z : expm1f(z);
}

extern "C" void kernel_launch(void* const* d_in, const int* in_sizes, int n_in,
                              void* d_out, int out_size){
    const float* h    = (const float*)d_in[0];
    const int*   mask = (const int*)  d_in[1];
    const float* W    = (const float*)d_in[2];
    const float* a    = (const float*)d_in[3];
    float* out = (float*)d_out;

    cudaFuncSetAttribute(k_attn, cudaFuncAttributeMaxDynamicSharedMemorySize, SMEM_BYTES);

    k_gemm<<<dim3(NN/64, KH), 256>>>(h, W);
    k_f<<<(KH*NN)/8, 256>>>(a);
    k_pack<<<(KH*(size_t)NN*NN/32)/64, 256>>>(mask);
    k_attn<<<dim3(NN/MT, KH, CS), 256, SMEM_BYTES>>>();
    k_comb<<<(NN*OF)/256, 256>>>(out);
}

// round 8
// speedup vs baseline: 1.0039x; 1.0025x over previous
#include <cuda_runtime.h>
#include <cstdint>

#define NN   4096
#define INF_ 256
#define OF   128
#define KH   3
#define ALPHA 0.2f
#define CS   4               // column splits
#define CPC  (NN/CS)         // cols per split (1024)
#define CT   64              // k-tile (cols per stage)
#define MT   128             // rows per block
#define NTILES (CPC/CT)      // 16
#define VPAD 136             // V_s row stride in floats (bank-conflict free)

// scratch (device globals — no allocation allowed)
__device__ float    g_Wh[KH][NN][OF];       // Whnew fp32
__device__ float    g_Vt[KH][NN][OF];       // Whnew pre-rounded to tf32
__device__ float4   g_EF[KH][NN];           // {exp(f1), exp(a*f1), exp(f2), exp(a*f2)}
__device__ unsigned g_mbits[KH][NN][NN/32]; // bit-packed mask
__device__ float    g_num[CS][KH][NN][OF];
__device__ float    g_den[CS][KH][NN];

__device__ __forceinline__ unsigned f2tf32(float x){
    unsigned r; asm("cvt.rna.tf32.f32 %0, %1;" : "=r"(r) : "f"(x)); return r;
}
__device__ __forceinline__ void mma_tf32(float (&d)[4], const unsigned (&a)[4],
                                         unsigned b0, unsigned b1){
    asm volatile("mma.sync.aligned.m16n8k8.row.col.f32.tf32.tf32.f32 "
        "{%0,%1,%2,%3},{%4,%5,%6,%7},{%8,%9},{%0,%1,%2,%3};\n"
        : "+f"(d[0]), "+f"(d[1]), "+f"(d[2]), "+f"(d[3])
        : "r"(a[0]), "r"(a[1]), "r"(a[2]), "r"(a[3]), "r"(b0), "r"(b1));
}
__device__ __forceinline__ void cpa16(void* dst, const void* src){
    unsigned d = (unsigned)__cvta_generic_to_shared(dst);
    asm volatile("cp.async.cg.shared.global [%0], [%1], 16;\n" :: "r"(d), "l"(src));
}
__device__ __forceinline__ void cpa8(void* dst, const void* src){
    unsigned d = (unsigned)__cvta_generic_to_shared(dst);
    asm volatile("cp.async.ca.shared.global [%0], [%1], 8;\n" :: "r"(d), "l"(src));
}

// ---------------- Kernel 0: pack mask into bits (streaming) ----------------
__global__ __launch_bounds__(256) void k_pack(const int* __restrict__ mask){
    size_t wbase = (size_t)blockIdx.x*64 + (size_t)(threadIdx.x>>5)*8;
    int l = threadIdx.x & 31;
    const int* p = mask + wbase*32;
    int v[8];
    #pragma unroll
    for (int i=0;i<8;i++) v[i] = p[(size_t)i*32 + l];
    unsigned b[8];
    #pragma unroll
    for (int i=0;i<8;i++) b[i] = __ballot_sync(0xffffffffu, v[i] > 0);
    if (l==0){
        unsigned* dst = ((unsigned*)g_mbits) + wbase;
        uint4 lo = make_uint4(b[0],b[1],b[2],b[3]);
        uint4 hi = make_uint4(b[4],b[5],b[6],b[7]);
        *(uint4*)(dst)   = lo;
        *(uint4*)(dst+4) = hi;
    }
}

// ---------------- Kernel 1: Whnew = h @ W_i (fp32) + tf32-rounded copy ----------------
__global__ __launch_bounds__(256) void k_gemm(const float* __restrict__ h,
                                              const float* __restrict__ W){
    int hop = blockIdx.y;
    int r0  = blockIdx.x * 64;
    __shared__ float hs[64][32];
    __shared__ float ws[32][128];
    int tid = threadIdx.x;
    int ty = tid >> 5, tx = tid & 31;
    float acc[8][4];
    #pragma unroll
    for (int i=0;i<8;i++){ acc[i][0]=0.f;acc[i][1]=0.f;acc[i][2]=0.f;acc[i][3]=0.f; }

    for (int k0=0; k0<INF_; k0+=32){
        #pragma unroll
        for (int i=0;i<2;i++){
            int f4 = tid + i*256;
            int row = f4>>3, c4 = f4&7;
            *(float4*)&hs[row][c4*4] =
                *(const float4*)&h[(size_t)(r0+row)*INF_ + k0 + c4*4];
        }
        #pragma unroll
        for (int i=0;i<4;i++){
            int f4 = tid + i*256;
            int row = f4>>5, c4 = f4&31;
            *(float4*)&ws[row][c4*4] =
                *(const float4*)&W[(size_t)(hop*INF_ + k0 + row)*OF + c4*4];
        }
        __syncthreads();
        #pragma unroll
        for (int k=0;k<32;k++){
            float4 w4 = *(const float4*)&ws[k][tx*4];
            #pragma unroll
            for (int ii=0;ii<8;ii++){
                float hv = hs[ty*8+ii][k];
                acc[ii][0] += hv*w4.x; acc[ii][1] += hv*w4.y;
                acc[ii][2] += hv*w4.z; acc[ii][3] += hv*w4.w;
            }
        }
        __syncthreads();
    }
    #pragma unroll
    for (int ii=0;ii<8;ii++){
        int r = r0 + ty*8 + ii;
        float4 o = make_float4(acc[ii][0],acc[ii][1],acc[ii][2],acc[ii][3]);
        *(float4*)&g_Wh[hop][r][tx*4] = o;
        float4 t = make_float4(__uint_as_float(f2tf32(o.x)), __uint_as_float(f2tf32(o.y)),
                               __uint_as_float(f2tf32(o.z)), __uint_as_float(f2tf32(o.w)));
        *(float4*)&g_Vt[hop][r][tx*4] = t;
    }
}

// ---------------- Kernel 2: f1,f2 per (hop,row) -> exp tables ----------------
__global__ __launch_bounds__(256) void k_f(const float* __restrict__ a){
    int gw   = blockIdx.x*8 + (threadIdx.x>>5);
    int lane = threadIdx.x & 31;
    int hop  = gw >> 12;
    int row  = gw & (NN-1);
    float4 wh = *(const float4*)&g_Wh[hop][row][lane*4];
    float4 a1 = *(const float4*)&a[(2*hop  )*OF + lane*4];
    float4 a2 = *(const float4*)&a[(2*hop+1)*OF + lane*4];
    float p1 = wh.x*a1.x + wh.y*a1.y + wh.z*a1.z + wh.w*a1.w;
    float p2 = wh.x*a2.x + wh.y*a2.y + wh.z*a2.z + wh.w*a2.w;
    #pragma unroll
    for (int o=16;o;o>>=1){
        p1 += __shfl_xor_sync(0xffffffffu,p1,o);
        p2 += __shfl_xor_sync(0xffffffffu,p2,o);
    }
    if (lane==0)
        g_EF[hop][row] = make_float4(expf(p1), expf(ALPHA*p1), expf(p2), expf(ALPHA*p2));
}

// ---------------- Kernel 3: fused masked-softmax-numerator @ V via tf32 MMA ----------------
// block = (rowblock MT=128, hop, colsplit); 256 threads = 8 warps, each owns one m16 group.
// Double-buffered cp.async pipeline for V tile / E2 / packed mask bits.
#define SM_V   (2*CT*VPAD)                    // floats
#define SM_E   (2*CT)                         // float4
#define SM_M   (2*MT)                         // uint2
#define SMEM_BYTES (SM_V*4 + SM_E*16 + SM_M*8)

__global__ __launch_bounds__(256, 2) void k_attn(){
    extern __shared__ char smem_raw[];
    float*  V_s = (float*)smem_raw;                       // [2][CT][VPAD]
    float4* E_s = (float4*)(smem_raw + SM_V*4);           // [2][CT]
    uint2*  M_s = (uint2*)(smem_raw + SM_V*4 + SM_E*16);  // [2][MT]

    const int hop = blockIdx.y, cs = blockIdx.z;
    const int rb  = blockIdx.x * MT;
    const int tid = threadIdx.x, w = tid>>5, l = tid&31;
    const int q4 = l>>2, t4 = l&3;

    // stage loader: full 64x128 V tile (8*256 float4), E2 chunk, mask bits
    auto stage = [&](int t, int b){
        int c0 = cs*CPC + t*CT;
        #pragma unroll
        for (int i=0;i<8;i++){
            int f4 = i*256 + tid;
            int row = f4>>5, c4 = f4&31;
            cpa16(&V_s[b*CT*VPAD + row*VPAD + c4*4], &g_Vt[hop][c0+row][c4*4]);
        }
        if (tid < CT)  cpa16(&E_s[b*CT + tid], &g_EF[hop][c0+tid]);
        if (tid < MT)  cpa8 (&M_s[b*MT + tid], &g_mbits[hop][rb+tid][c0>>5]);
        asm volatile("cp.async.commit_group;\n");
    };

    // per-warp row constants
    const int r0 = rb + w*16 + q4, r1 = r0 + 8;
    float4 ef0 = g_EF[hop][r0];
    float4 ef1 = g_EF[hop][r1];
    const float e1p0 = ef0.x, e1n0 = ef0.y, e1p1 = ef1.x, e1n1 = ef1.y;

    float acc[16][4];
    #pragma unroll
    for (int n=0;n<16;n++){ acc[n][0]=0;acc[n][1]=0;acc[n][2]=0;acc[n][3]=0; }
    float dsum0 = 0.f, dsum1 = 0.f;

    stage(0, 0);

    for (int t=0; t<NTILES; t++){
        int b = t & 1;
        if (t+1 < NTILES){
            stage(t+1, (t+1)&1);
            asm volatile("cp.async.wait_group 1;\n");
        } else {
            asm volatile("cp.async.wait_group 0;\n");
        }
        __syncthreads();

        uint2 mw0 = M_s[b*MT + w*16 + q4];
        uint2 mw1 = M_s[b*MT + w*16 + q4 + 8];
        const float* Vb = V_s + b*CT*VPAD;
        const float4* Eb = E_s + b*CT;

        #pragma unroll
        for (int k2=0;k2<8;k2++){
            const int cb = k2*8;
            float4 eA = Eb[cb + t4];
            float4 eB = Eb[cb + t4 + 4];
            float v00 = fmaxf(e1p0*eA.z, e1n0*eA.w);
            float v10 = fmaxf(e1p1*eA.z, e1n1*eA.w);
            float v01 = fmaxf(e1p0*eB.z, e1n0*eB.w);
            float v11 = fmaxf(e1p1*eB.z, e1n1*eB.w);
            // mask bit selection (word chosen at compile time per k2)
            unsigned wA0 = (k2<4)? mw0.x : mw0.y;
            unsigned wA1 = (k2<4)? mw1.x : mw1.y;
            unsigned wB0 = (k2<4)? mw0.x : mw0.y;   // cb+t4+4 <=31 for k2<=3
            unsigned wB1 = (k2<4)? mw1.x : mw1.y;
            int shA = (cb + t4) & 31;
            int shB = (cb + t4 + 4) & 31;
            unsigned fr[4];
            fr[0] = ((wA0>>shA)&1u) ? f2tf32(v00) : 0u;
            fr[1] = ((wA1>>shA)&1u) ? f2tf32(v10) : 0u;
            fr[2] = ((wB0>>shB)&1u) ? f2tf32(v01) : 0u;
            fr[3] = ((wB1>>shB)&1u) ? f2tf32(v11) : 0u;
            dsum0 += __uint_as_float(fr[0]) + __uint_as_float(fr[2]);
            dsum1 += __uint_as_float(fr[1]) + __uint_as_float(fr[3]);

            const float* vr0 = Vb + (cb+t4)*VPAD + q4;
            const float* vr1 = Vb + (cb+t4+4)*VPAD + q4;
            #pragma unroll
            for (int n=0;n<16;n++){
                mma_tf32(acc[n], fr,
                         __float_as_uint(vr0[n*8]),
                         __float_as_uint(vr1[n*8]));
            }
        }
        __syncthreads();
    }

    // denominators: reduce across t4 lanes (same rows)
    dsum0 += __shfl_xor_sync(0xffffffffu, dsum0, 1);
    dsum0 += __shfl_xor_sync(0xffffffffu, dsum0, 2);
    dsum1 += __shfl_xor_sync(0xffffffffu, dsum1, 1);
    dsum1 += __shfl_xor_sync(0xffffffffu, dsum1, 2);
    if (t4 == 0){
        g_den[cs][hop][r0] = dsum0;
        g_den[cs][hop][r1] = dsum1;
    }
    // numerators
    #pragma unroll
    for (int n=0;n<16;n++){
        int gc = n*8 + 2*t4;
        float2 lo; lo.x = acc[n][0]; lo.y = acc[n][1];
        float2 hi; hi.x = acc[n][2]; hi.y = acc[n][3];
        *(float2*)&g_num[cs][hop][r0][gc] = lo;
        *(float2*)&g_num[cs][hop][r1][gc] = hi;
    }
}

// ---------------- Kernel 4: combine hops + elu ----------------
__global__ __launch_bounds__(256) void k_comb(float* __restrict__ out){
    int idx = blockIdx.x*256 + threadIdx.x;
    int r = idx >> 7, c = idx & (OF-1);
    float z = 0.125f * g_Wh[2][r][c];
    float coef = 0.5f;
    #pragma unroll
    for (int h2=0; h2<KH; h2++){
        float num = 0.f, den = 1e-30f;
        #pragma unroll
        for (int s=0;s<CS;s++){ num += g_num[s][h2][r][c]; den += g_den[s][h2][r]; }
        z += coef * num / den;
        coef *= 0.5f;
    }
    out[idx] = (z > 0.f) ? z : expm1f(z);
}

extern "C" void kernel_launch(void* const* d_in, const int* in_sizes, int n_in,
                              void* d_out, int out_size){
    const float* h    = (const float*)d_in[0];
    const int*   mask = (const int*)  d_in[1];
    const float* W    = (const float*)d_in[2];
    const float* a    = (const float*)d_in[3];
    float* out = (float*)d_out;

    cudaFuncSetAttribute(k_attn, cudaFuncAttributeMaxDynamicSharedMemorySize, SMEM_BYTES);

    k_gemm<<<dim3(NN/64, KH), 256>>>(h, W);
    k_f<<<(KH*NN)/8, 256>>>(a);
    k_pack<<<(KH*(size_t)NN*NN/32)/64, 256>>>(mask);
    k_attn<<<dim3(NN/MT, KH, CS), 256, SMEM_BYTES>>>();
    k_comb<<<(NN*OF)/256, 256>>>(out);
}